// round 8
// baseline (speedup 1.0000x reference)
#include <cuda_runtime.h>

// Shapes (fixed)
#define Bn 16
#define In 32
#define Cn 8
#define Jn 10
#define Dn 16
#define Xn 576   // D*H*W
#define XH 288   // half handled per CTA
#define HWn 36
#define EPSf 1e-7f
#define GRID (Bn*Jn*2)   // 320 CTAs

// Scratch (device globals)
__device__ float    g_U[(size_t)Bn*Jn*In*Xn];  // [bj][i][x], 11.8 MB (L2-resident)
__device__ float    g_nPart[2][GRID];          // per-(b,j,half) L1-norm partials
__device__ float    g_aPart[2][GRID * In];     // [entry][i], i contiguous (128B rows)
__device__ unsigned g_cnt;                     // barrier counter (self-resetting)
__device__ unsigned g_gen;                     // barrier generation (monotonic)

__device__ __forceinline__ float squash_k(float n) {
    float n2 = n * n;
    return (n2 / (1.f + n2)) / (n + EPSf);
}

// Grid barrier (k_rest only; its 320 CTAs are co-resident via launch_bounds>=3/SM).
__device__ __forceinline__ void gridBarrier() {
    __threadfence();
    __syncthreads();
    if (threadIdx.x == 0) {
        unsigned g0 = *(volatile unsigned*)&g_gen;
        unsigned a = atomicAdd(&g_cnt, 1u);
        if (a == GRID - 1) {
            atomicExch(&g_cnt, 0u);
            __threadfence();
            atomicAdd(&g_gen, 1u);
        } else {
            while (*(volatile unsigned*)&g_gen == g0) { }
        }
        __threadfence();
    }
    __syncthreads();
}

// Block sum over 288 threads; valid on thread 0.
__device__ __forceinline__ float blockReduceSum288(float v) {
    __shared__ float red[9];
    int lane = threadIdx.x & 31, w = threadIdx.x >> 5;
    #pragma unroll
    for (int o = 16; o > 0; o >>= 1) v += __shfl_down_sync(0xffffffffu, v, o);
    if (lane == 0) red[w] = v;
    __syncthreads();
    float s = 0.f;
    if (threadIdx.x == 0) {
        #pragma unroll
        for (int k = 0; k < 9; k++) s += red[k];
    }
    return s;
}

// ---------------------------------------------------------------------------
// Kernel A (measured 14us in R6): stream u_hat once (94 MB), write U (L2),
// fuse iteration-1 s / L1-norm / agreement partials (c1 == 1/J exactly).
// Uncapped registers, no barrier. grid = 320, block = 288.
__global__ void __launch_bounds__(XH) k_load(const float* __restrict__ u,
                                             const float* __restrict__ bias) {
    __shared__ __align__(16) float Us[In][XH];
    __shared__ float ss[XH];
    int bj = blockIdx.x >> 1, half = blockIdx.x & 1;
    int b = bj / Jn, j = bj % Jn;
    int x = threadIdx.x;
    int xg = half * XH + x;
    int w = x >> 5, lane = x & 31;

    // float4 remap: 4 i-groups x 72 float4-columns
    int t4 = x % 72, g = x / 72;
    int xq = half * XH + t4 * 4;
    const float* base = u + (size_t)b * In * Cn * Jn * Xn + (size_t)j * Xn + xq;
    float* uout = &g_U[(size_t)bj * In * Xn + xq];
    #pragma unroll 2
    for (int ii = 0; ii < 8; ii++) {
        int i = g * 8 + ii;
        const float4* p = (const float4*)(base + (size_t)i * Cn * Jn * Xn);
        float4 a0 = __ldcs(p);
        float4 a1 = __ldcs(p + 1 * (Jn * Xn / 4));
        float4 a2 = __ldcs(p + 2 * (Jn * Xn / 4));
        float4 a3 = __ldcs(p + 3 * (Jn * Xn / 4));
        float4 a4 = __ldcs(p + 4 * (Jn * Xn / 4));
        float4 a5 = __ldcs(p + 5 * (Jn * Xn / 4));
        float4 a6 = __ldcs(p + 6 * (Jn * Xn / 4));
        float4 a7 = __ldcs(p + 7 * (Jn * Xn / 4));
        float4 acc;
        acc.x = ((a0.x + a1.x) + (a2.x + a3.x)) + ((a4.x + a5.x) + (a6.x + a7.x));
        acc.y = ((a0.y + a1.y) + (a2.y + a3.y)) + ((a4.y + a5.y) + (a6.y + a7.y));
        acc.z = ((a0.z + a1.z) + (a2.z + a3.z)) + ((a4.z + a5.z) + (a6.z + a7.z));
        acc.w = ((a0.w + a1.w) + (a2.w + a3.w)) + ((a4.w + a5.w) + (a6.w + a7.w));
        *(float4*)&Us[i][t4 * 4] = acc;
        *(float4*)(uout + (size_t)i * Xn) = acc;   // plain store -> stays in L2
    }
    __syncthreads();

    // s1 = (1/J) * sum_i U + bias
    float acc = 0.f;
    #pragma unroll
    for (int i = 0; i < In; i++) acc += Us[i][x];
    float s = acc * (1.0f / Jn) + bias[j * Dn + xg / HWn];

    float n = blockReduceSum288(fabsf(s));
    if (x == 0) g_nPart[0][blockIdx.x] = n;

    ss[x] = s;
    __syncthreads();
    // unscaled agreement partials for iteration 1 (layout [entry][i])
    if (w < 8) {
        #pragma unroll
        for (int ii = 0; ii < 4; ii++) {
            int i = w * 4 + ii;
            float a = 0.f;
            #pragma unroll
            for (int xx = lane; xx < XH; xx += 32) a += Us[i][xx] * ss[xx];
            #pragma unroll
            for (int o = 16; o > 0; o >>= 1) a += __shfl_down_sync(0xffffffffu, a, o);
            if (lane == 0) g_aPart[0][(size_t)blockIdx.x * In + i] = a;
        }
    }
}

// ---------------------------------------------------------------------------
// Kernel B: reload U once (L2-hot), iterations 2-3 with COALESCED routing
// updates (warp=j, lane=i, 128B rows), 2 internal grid barriers, final output.
// grid = 320, block = 288, >=3 CTAs/SM for barrier co-residency.
__global__ void __launch_bounds__(XH, 3) k_rest(const float* __restrict__ bias,
                                                float* __restrict__ out) {
    __shared__ __align__(16) float Us[In][XH];
    __shared__ float ss[XH];
    __shared__ float sb[In * Jn];
    __shared__ float cs[In];
    __shared__ float kb_sh[Bn];
    int bj = blockIdx.x >> 1, half = blockIdx.x & 1;
    int b = bj / Jn, j = bj % Jn;
    int x = threadIdx.x;
    int xg = half * XH + x;
    int w = x >> 5, lane = x & 31;
    float biasv = bias[j * Dn + xg / HWn];

    // load U tile (float4, L2 hits)
    {
        int t4 = x % 72, g = x / 72;
        int xq = half * XH + t4 * 4;
        #pragma unroll
        for (int ii = 0; ii < 8; ii++) {
            int i = g * 8 + ii;
            float4 v = __ldcg((const float4*)&g_U[((size_t)bj * In + i) * Xn + xq]);
            *(float4*)&Us[i][t4 * 4] = v;
        }
    }
    for (int t = x; t < In * Jn; t += XH) sb[t] = 0.f;
    __syncthreads();

    float s = 0.f;
    #pragma unroll 1
    for (int iter = 1; iter < 3; iter++) {
        int prev = (iter - 1) & 1;    // partials from previous stage

        // ---- routing update: kb from prev norms, coalesced agreement reads
        if (x < Bn) {
            float nn = 0.f;
            #pragma unroll
            for (int t = 0; t < Jn * 2; t++) nn += __ldcg(&g_nPart[prev][x * Jn * 2 + t]);
            kb_sh[x] = squash_k(nn);
        }
        __syncthreads();
        for (int jj = w; jj < Jn; jj += 9) {
            float a = 0.f;
            #pragma unroll
            for (int bh = 0; bh < Bn * 2; bh++) {
                int bb = bh >> 1;
                int ent = (bb * Jn + jj) * 2 + (bh & 1);
                a += kb_sh[bb] * __ldcg(&g_aPart[prev][(size_t)ent * In + lane]);
            }
            sb[lane * Jn + jj] += a;
        }
        __syncthreads();
        if (x < In) {
            float mx = -1e30f;
            #pragma unroll
            for (int jj = 0; jj < Jn; jj++) mx = fmaxf(mx, sb[x * Jn + jj]);
            float den = 0.f;
            #pragma unroll
            for (int jj = 0; jj < Jn; jj++) den += expf(sb[x * Jn + jj] - mx);
            cs[x] = expf(sb[x * Jn + j] - mx) / den;
        }
        __syncthreads();

        // ---- s for this iteration
        float acc = 0.f;
        #pragma unroll
        for (int i = 0; i < In; i++) acc += cs[i] * Us[i][x];
        s = acc + biasv;

        float n = blockReduceSum288(fabsf(s));
        if (x == 0) g_nPart[iter & 1][blockIdx.x] = n;

        if (iter == 2) break;         // final agreement is dead

        ss[x] = s;
        __syncthreads();
        if (w < 8) {
            #pragma unroll
            for (int ii = 0; ii < 4; ii++) {
                int i = w * 4 + ii;
                float a = 0.f;
                #pragma unroll
                for (int xx = lane; xx < XH; xx += 32) a += Us[i][xx] * ss[xx];
                #pragma unroll
                for (int o = 16; o > 0; o >>= 1) a += __shfl_down_sync(0xffffffffu, a, o);
                if (lane == 0) g_aPart[iter & 1][(size_t)blockIdx.x * In + i] = a;
            }
        }
        gridBarrier();
    }

    // ---- final squash (iter-2 norms are in buffer 0)
    gridBarrier();
    if (x == 0) {
        float nn = 0.f;
        #pragma unroll
        for (int t = 0; t < Jn * 2; t++) nn += __ldcg(&g_nPart[0][b * Jn * 2 + t]);
        kb_sh[0] = squash_k(nn);
    }
    __syncthreads();
    out[(size_t)bj * Xn + xg] = kb_sh[0] * s;
}

extern "C" void kernel_launch(void* const* d_in, const int* in_sizes, int n_in,
                              void* d_out, int out_size) {
    const float* u    = (const float*)d_in[0];
    const float* bias = (const float*)d_in[1];
    float* out = (float*)d_out;
    k_load<<<GRID, XH>>>(u, bias);
    k_rest<<<GRID, XH>>>(bias, out);
}

// round 9
// speedup vs baseline: 1.6737x; 1.6737x over previous
#include <cuda_runtime.h>

// Shapes (fixed)
#define Bn 16
#define In 32
#define Cn 8
#define Jn 10
#define Dn 16
#define Xn 576   // D*H*W (one CTA owns a full (b,j) slice)
#define NT 288   // threads per CTA; each owns x and x+288
#define HWn 36
#define EPSf 1e-7f
#define GRID2 (Bn*Jn)   // 160 CTAs -> co-residency needs only 2 CTAs/SM (113 regs!)

// Cross-CTA comm scratch, parity double-buffered (WAR safety across the single
// per-iteration grid barrier).
__device__ float    g_nPart[2][GRID2];         // per-(b,j) L1-norm of s
__device__ float    g_aPart[2][GRID2 * In];    // [entry][i], i contiguous (128B rows)
__device__ unsigned g_cnt;
__device__ unsigned g_gen;

__device__ __forceinline__ float squash_k(float n) {
    float n2 = n * n;
    return (n2 / (1.f + n2)) / (n + EPSf);
}

// Grid barrier. 160 CTAs co-resident (160 <= 148*2; launch_bounds >=2/SM and
// smem fits exactly 2/SM).
__device__ __forceinline__ void gridBarrier() {
    __threadfence();
    __syncthreads();
    if (threadIdx.x == 0) {
        unsigned g0 = *(volatile unsigned*)&g_gen;
        unsigned a = atomicAdd(&g_cnt, 1u);
        if (a == GRID2 - 1) {
            atomicExch(&g_cnt, 0u);
            __threadfence();
            atomicAdd(&g_gen, 1u);
        } else {
            while (*(volatile unsigned*)&g_gen == g0) { }
        }
        __threadfence();
    }
    __syncthreads();
}

// Block sum over 288 threads; valid on thread 0.
__device__ __forceinline__ float blockReduceSum288(float v) {
    __shared__ float red[9];
    int lane = threadIdx.x & 31, w = threadIdx.x >> 5;
    #pragma unroll
    for (int o = 16; o > 0; o >>= 1) v += __shfl_down_sync(0xffffffffu, v, o);
    if (lane == 0) red[w] = v;
    __syncthreads();
    float s = 0.f;
    if (threadIdx.x == 0) {
        #pragma unroll
        for (int k = 0; k < 9; k++) s += red[k];
    }
    return s;
}

__global__ void __launch_bounds__(NT, 2) routing_all(
    const float* __restrict__ u, const float* __restrict__ bias,
    float* __restrict__ out)
{
    // U tile for the full (b,j) slice: 32 x 576 floats = 73,728 B (dynamic smem)
    extern __shared__ __align__(16) float Us[];   // Us[i*Xn + x]
    __shared__ float ss[Xn];
    __shared__ float sb[In * Jn];     // routing logits (identical in all CTAs)
    __shared__ float cs[In];          // coupling coeffs for this CTA's j
    __shared__ float kb_sh[Bn];
    int bj = blockIdx.x;
    int b = bj / Jn, j = bj % Jn;
    int x = threadIdx.x;
    int w = x >> 5, lane = x & 31;
    float bias0 = bias[j * Dn + x / HWn];
    float bias1 = bias[j * Dn + (x + NT) / HWn];

    for (int t = x; t < In * Jn; t += NT) sb[t] = 0.f;

    // ---- Load phase: Us[i][x] = sum_c u_hat[b,i,c,j,x]. 94 MB streamed once.
    // 2 i-groups x 144 float4-cols; 113-reg budget -> 16 float4 loads in flight.
    {
        int t4 = x % 144, g = x / 144;        // g in {0,1}, 16 i's each
        int xq = t4 * 4;
        const float* base = u + (size_t)b * In * Cn * Jn * Xn + (size_t)j * Xn + xq;
        #pragma unroll 2
        for (int ii = 0; ii < 16; ii++) {
            int i = g * 16 + ii;
            const float4* p = (const float4*)(base + (size_t)i * Cn * Jn * Xn);
            float4 a0 = __ldcs(p);
            float4 a1 = __ldcs(p + 1 * (Jn * Xn / 4));
            float4 a2 = __ldcs(p + 2 * (Jn * Xn / 4));
            float4 a3 = __ldcs(p + 3 * (Jn * Xn / 4));
            float4 a4 = __ldcs(p + 4 * (Jn * Xn / 4));
            float4 a5 = __ldcs(p + 5 * (Jn * Xn / 4));
            float4 a6 = __ldcs(p + 6 * (Jn * Xn / 4));
            float4 a7 = __ldcs(p + 7 * (Jn * Xn / 4));
            float4 acc;
            acc.x = ((a0.x + a1.x) + (a2.x + a3.x)) + ((a4.x + a5.x) + (a6.x + a7.x));
            acc.y = ((a0.y + a1.y) + (a2.y + a3.y)) + ((a4.y + a5.y) + (a6.y + a7.y));
            acc.z = ((a0.z + a1.z) + (a2.z + a3.z)) + ((a4.z + a5.z) + (a6.z + a7.z));
            acc.w = ((a0.w + a1.w) + (a2.w + a3.w)) + ((a4.w + a5.w) + (a6.w + a7.w));
            *(float4*)&Us[i * Xn + xq] = acc;
        }
    }
    __syncthreads();

    float s0 = 0.f, s1 = 0.f;
    #pragma unroll 1
    for (int iter = 0; iter < 3; iter++) {
        int pb = iter & 1;

        // ---- routing update from previous iteration's partials (iter > 0).
        // Coalesced: lane = i, each g_aPart entry row is one 128B line.
        if (iter > 0) {
            int prev = (iter - 1) & 1;
            if (x < Bn) {
                float nn = 0.f;
                #pragma unroll
                for (int t = 0; t < Jn; t++) nn += __ldcg(&g_nPart[prev][x * Jn + t]);
                kb_sh[x] = squash_k(nn);
            }
            __syncthreads();
            for (int jj = w; jj < Jn; jj += 9) {
                float a = 0.f;
                #pragma unroll
                for (int bb = 0; bb < Bn; bb++) {
                    int ent = bb * Jn + jj;
                    a += kb_sh[bb] * __ldcg(&g_aPart[prev][(size_t)ent * In + lane]);
                }
                sb[lane * Jn + jj] += a;      // b_ij += agreement
            }
            __syncthreads();
            if (x < In) {
                float mx = -1e30f;
                #pragma unroll
                for (int jj = 0; jj < Jn; jj++) mx = fmaxf(mx, sb[x * Jn + jj]);
                float den = 0.f;
                #pragma unroll
                for (int jj = 0; jj < Jn; jj++) den += expf(sb[x * Jn + jj] - mx);
                cs[x] = expf(sb[x * Jn + j] - mx) / den;
            }
            __syncthreads();
        }

        // ---- s_j for this (b,j): thread owns x and x+288
        if (iter == 0) {
            float a0 = 0.f, a1 = 0.f;
            #pragma unroll
            for (int i = 0; i < In; i++) {
                a0 += Us[i * Xn + x];
                a1 += Us[i * Xn + x + NT];
            }
            s0 = a0 * (1.0f / Jn) + bias0;    // softmax(0) = 1/J exactly
            s1 = a1 * (1.0f / Jn) + bias1;
        } else {
            float a0 = 0.f, a1 = 0.f;
            #pragma unroll
            for (int i = 0; i < In; i++) {
                float c = cs[i];
                a0 += c * Us[i * Xn + x];
                a1 += c * Us[i * Xn + x + NT];
            }
            s0 = a0 + bias0;
            s1 = a1 + bias1;
        }
        // ---- L1-norm (full (b,j) slice in one CTA now)
        float n = blockReduceSum288(fabsf(s0) + fabsf(s1));
        if (x == 0) g_nPart[pb][bj] = n;

        if (iter == 2) break;                 // final agreement is dead

        ss[x] = s0;
        ss[x + NT] = s1;
        __syncthreads();
        // ---- unscaled agreement partials: aU[i] = sum_x Us[i][x]*ss[x]
        if (w < 8) {
            #pragma unroll
            for (int ii = 0; ii < 4; ii++) {
                int i = w * 4 + ii;
                float a = 0.f;
                #pragma unroll
                for (int xx = lane; xx < Xn; xx += 32) a += Us[i * Xn + xx] * ss[xx];
                #pragma unroll
                for (int o = 16; o > 0; o >>= 1) a += __shfl_down_sync(0xffffffffu, a, o);
                if (lane == 0) g_aPart[pb][(size_t)bj * In + i] = a;
            }
        }
        gridBarrier();
    }

    // ---- final squash (iter-2 norms are in buffer 0)
    gridBarrier();
    if (x == 0) {
        float nn = 0.f;
        #pragma unroll
        for (int t = 0; t < Jn; t++) nn += __ldcg(&g_nPart[0][b * Jn + t]);
        kb_sh[0] = squash_k(nn);
    }
    __syncthreads();
    float kb = kb_sh[0];
    out[(size_t)bj * Xn + x]      = kb * s0;
    out[(size_t)bj * Xn + x + NT] = kb * s1;
}

extern "C" void kernel_launch(void* const* d_in, const int* in_sizes, int n_in,
                              void* d_out, int out_size) {
    const float* u    = (const float*)d_in[0];
    const float* bias = (const float*)d_in[1];
    float* out = (float*)d_out;
    const int dyn_smem = In * Xn * sizeof(float);   // 73,728 B
    cudaFuncSetAttribute(routing_all,
                         cudaFuncAttributeMaxDynamicSharedMemorySize, dyn_smem);
    routing_all<<<GRID2, NT, dyn_smem>>>(u, bias, out);
}